// round 1
// baseline (speedup 1.0000x reference)
#include <cuda_runtime.h>
#include <math.h>

// Problem constants (fixed by the reference)
#define NN 50000
#define EE 800000
#define HH 128
#define LL 3
#define NT 256          // threads per block for GEMM kernels
#define EPSBN 1e-5f

// ---------------- scratch (static device globals; no allocation) ----------
__device__ float g_h[NN * HH];     // node features
__device__ float g_p[NN * HH];     // P = h @ W1a_top
__device__ float g_agg[NN * HH];   // edge aggregation (sums)
__device__ float g_r[NN * HH];     // residual pre-BN
__device__ float g_inv[NN];        // 1 / max(indeg, 1)
__device__ int   g_cnt[NN];        // in-degree
__device__ float g_sum[HH];        // BN column sums
__device__ float g_sq[HH];         // BN column sum-of-squares

// ---------------- shared tiled GEMM core ----------------------------------
// C-tile = A(smem, rows=16*RPT, stride lda) @ W(global, K x 128)
// 256 threads: ty=tid/16 row-group, tx=tid%16 col-group (8 cols each).
// W is staged in 16-row chunks through Ws (16*128 floats).
template<int RPT>
__device__ __forceinline__ void gemm_acc(const float* As, int lda, float* Ws,
                                         const float* __restrict__ Wg, int K,
                                         float acc[RPT][8], int tid)
{
    const int ty = tid >> 4, tx = tid & 15;
    for (int kc = 0; kc < K; kc += 16) {
        __syncthreads();   // protect Ws (and prior As writes)
        for (int t = tid; t < 512; t += NT) {
            int kk = t >> 5, j4 = (t & 31) << 2;
            *(float4*)(Ws + kk * HH + j4) =
                *(const float4*)(Wg + (size_t)(kc + kk) * HH + j4);
        }
        __syncthreads();
        #pragma unroll
        for (int k = 0; k < 16; ++k) {
            float a[RPT];
            #pragma unroll
            for (int i = 0; i < RPT; ++i) a[i] = As[(ty * RPT + i) * lda + kc + k];
            float4 b0 = *(const float4*)(Ws + k * HH + tx * 8);
            float4 b1 = *(const float4*)(Ws + k * HH + tx * 8 + 4);
            float bb[8] = {b0.x, b0.y, b0.z, b0.w, b1.x, b1.y, b1.z, b1.w};
            #pragma unroll
            for (int i = 0; i < RPT; ++i)
                #pragma unroll
                for (int j = 0; j < 8; ++j)
                    acc[i][j] = fmaf(a[i], bb[j], acc[i][j]);
        }
    }
    __syncthreads();   // callers may overwrite As after return
}

// ---------------- input MLP: h = relu(relu(x@W0+b0)@W1+b1) ----------------
__global__ __launch_bounds__(NT) void k_input(
    const float* __restrict__ x,
    const float* __restrict__ W0, const float* __restrict__ b0,
    const float* __restrict__ W1, const float* __restrict__ b1, int n)
{
    extern __shared__ float smem[];
    float* As  = smem;             // 64*132
    float* Ws  = As + 64 * 132;    // 16*128
    float* w0s = Ws + 2048;        // 2*128
    float* b0s = w0s + 256;        // 128
    float* xs  = b0s + 128;        // 64*2
    const int tid = threadIdx.x;
    const int base = blockIdx.x * 64;

    for (int t = tid; t < 256; t += NT) w0s[t] = W0[t];
    for (int t = tid; t < 128; t += NT) b0s[t] = b0[t];
    if (tid < 128) {
        int row = tid >> 1;
        xs[tid] = (base + row < n) ? x[(size_t)(base + row) * 2 + (tid & 1)] : 0.f;
    }
    __syncthreads();

    // h1 tile directly into As
    for (int t = tid; t < 64 * 32; t += NT) {
        int row = t >> 5, j = (t & 31) << 2;
        float x0 = xs[row * 2], x1 = xs[row * 2 + 1];
        float4 v;
        v.x = fmaxf(fmaf(x0, w0s[j + 0], fmaf(x1, w0s[128 + j + 0], b0s[j + 0])), 0.f);
        v.y = fmaxf(fmaf(x0, w0s[j + 1], fmaf(x1, w0s[128 + j + 1], b0s[j + 1])), 0.f);
        v.z = fmaxf(fmaf(x0, w0s[j + 2], fmaf(x1, w0s[128 + j + 2], b0s[j + 2])), 0.f);
        v.w = fmaxf(fmaf(x0, w0s[j + 3], fmaf(x1, w0s[128 + j + 3], b0s[j + 3])), 0.f);
        *(float4*)(As + row * 132 + j) = v;
    }

    float acc[4][8] = {};
    gemm_acc<4>(As, 132, Ws, W1, HH, acc, tid);

    const int ty = tid >> 4, tx = tid & 15, c0 = tx * 8;
    #pragma unroll
    for (int i = 0; i < 4; ++i) {
        int row = base + ty * 4 + i;
        if (row < n) {
            #pragma unroll
            for (int j = 0; j < 8; ++j)
                g_h[(size_t)row * HH + c0 + j] = fmaxf(acc[i][j] + b1[c0 + j], 0.f);
        }
    }
}

// ---------------- P = h @ W1a_top (no bias / activation) -------------------
__global__ __launch_bounds__(NT) void k_precompute(
    const float* __restrict__ W, int n)
{
    extern __shared__ float smem[];
    float* As = smem;
    float* Ws = As + 64 * 132;
    const int tid = threadIdx.x;
    const int base = blockIdx.x * 64;

    for (int t = tid; t < 64 * 32; t += NT) {
        int row = t >> 5, j = (t & 31) << 2;
        float4 v = make_float4(0.f, 0.f, 0.f, 0.f);
        if (base + row < n) v = *(const float4*)(g_h + (size_t)(base + row) * HH + j);
        *(float4*)(As + row * 132 + j) = v;
    }

    float acc[4][8] = {};
    gemm_acc<4>(As, 132, Ws, W, HH, acc, tid);

    const int ty = tid >> 4, tx = tid & 15, c0 = tx * 8;
    #pragma unroll
    for (int i = 0; i < 4; ++i) {
        int row = base + ty * 4 + i;
        if (row < n) {
            #pragma unroll
            for (int j = 0; j < 8; ++j)
                g_p[(size_t)row * HH + c0 + j] = acc[i][j];
        }
    }
}

// ---------------- edge kernel: gather P, rank-2 + ReLU, GEMM, scatter ------
__global__ __launch_bounds__(NT) void k_edge(
    const float* __restrict__ ea,
    const int* __restrict__ src, const int* __restrict__ dst,
    const float* __restrict__ Wtail,   // rows 128,129 of W1a[l]
    const float* __restrict__ b1a,
    const float* __restrict__ W1b, const float* __restrict__ b1b, int E)
{
    extern __shared__ float smem[];
    float* As  = smem;             // 64*132
    float* Ws  = As + 64 * 132;    // 16*128
    float* wt  = Ws + 2048;        // 2*128
    float* bs  = wt + 256;         // 128
    float* eas = bs + 128;         // 64*2
    int*   sd  = (int*)(eas + 128); // src 64 + dst 64
    const int tid = threadIdx.x;
    const int e0 = blockIdx.x * 64;

    for (int t = tid; t < 256; t += NT) wt[t] = Wtail[t];
    for (int t = tid; t < 128; t += NT) bs[t] = b1a[t];
    if (tid < 64) {
        int e = e0 + tid;
        if (e < E) {
            sd[tid]       = src[e];
            sd[64 + tid]  = dst[e];
            eas[2 * tid]     = ea[(size_t)e * 2];
            eas[2 * tid + 1] = ea[(size_t)e * 2 + 1];
        } else {
            sd[tid] = 0; sd[64 + tid] = -1;
            eas[2 * tid] = 0.f; eas[2 * tid + 1] = 0.f;
        }
    }
    __syncthreads();

    // gather + fused rank-2 + bias + ReLU => m tile in As
    for (int t = tid; t < 64 * 32; t += NT) {
        int row = t >> 5, j = (t & 31) << 2;
        const float4 p = *(const float4*)(g_p + (size_t)sd[row] * HH + j);
        float ea0 = eas[2 * row], ea1 = eas[2 * row + 1];
        float4 m;
        m.x = fmaxf(p.x + ea0 * wt[j + 0] + ea1 * wt[128 + j + 0] + bs[j + 0], 0.f);
        m.y = fmaxf(p.y + ea0 * wt[j + 1] + ea1 * wt[128 + j + 1] + bs[j + 1], 0.f);
        m.z = fmaxf(p.z + ea0 * wt[j + 2] + ea1 * wt[128 + j + 2] + bs[j + 2], 0.f);
        m.w = fmaxf(p.w + ea0 * wt[j + 3] + ea1 * wt[128 + j + 3] + bs[j + 3], 0.f);
        *(float4*)(As + row * 132 + j) = m;
    }

    float acc[4][8] = {};
    gemm_acc<4>(As, 132, Ws, W1b, HH, acc, tid);

    const int ty = tid >> 4, tx = tid & 15, c0 = tx * 8;
    #pragma unroll
    for (int i = 0; i < 4; ++i) {
        int d = sd[64 + ty * 4 + i];
        if (d >= 0) {
            float* ab = g_agg + (size_t)d * HH + c0;
            #pragma unroll
            for (int j = 0; j < 8; ++j)
                atomicAdd(ab + j, fmaxf(acc[i][j] + b1b[c0 + j], 0.f));
        }
    }
}

// ---------------- node update: u=relu([h,agg/d]@W2a+b), out=sig(u@W2b+b),
//                  r = h + out, accumulate BN sums ------------------------
// 32-row tile to stay under 48KB smem.
__global__ __launch_bounds__(NT) void k_update(
    const float* __restrict__ W2a, const float* __restrict__ b2a,
    const float* __restrict__ W2b, const float* __restrict__ b2b, int n)
{
    extern __shared__ float smem[];
    const int LDA = 268;           // 256 + pad
    float* As = smem;              // 32*268
    float* Ws = As + 32 * LDA;     // 16*128
    const int tid = threadIdx.x;
    const int base = blockIdx.x * 32;

    for (int t = tid; t < 32 * 32; t += NT) {
        int row = t >> 5, j = (t & 31) << 2;
        float4 hv = make_float4(0.f, 0.f, 0.f, 0.f);
        float4 av = hv;
        if (base + row < n) {
            hv = *(const float4*)(g_h + (size_t)(base + row) * HH + j);
            av = *(const float4*)(g_agg + (size_t)(base + row) * HH + j);
            float iv = g_inv[base + row];
            av.x *= iv; av.y *= iv; av.z *= iv; av.w *= iv;
        }
        *(float4*)(As + row * LDA + j) = hv;
        *(float4*)(As + row * LDA + 128 + j) = av;
    }

    float acc[2][8] = {};
    gemm_acc<2>(As, LDA, Ws, W2a, 2 * HH, acc, tid);

    const int ty = tid >> 4, tx = tid & 15, c0 = tx * 8;
    // u overwrites the agg half of As
    #pragma unroll
    for (int i = 0; i < 2; ++i) {
        int row = ty * 2 + i;
        #pragma unroll
        for (int j = 0; j < 8; ++j)
            As[row * LDA + 128 + c0 + j] = fmaxf(acc[i][j] + b2a[c0 + j], 0.f);
    }

    float acc2[2][8] = {};
    gemm_acc<2>(As + 128, LDA, Ws, W2b, HH, acc2, tid);

    float s[8] = {}, s2[8] = {};
    #pragma unroll
    for (int i = 0; i < 2; ++i) {
        int row = base + ty * 2 + i;
        if (row < n) {
            #pragma unroll
            for (int j = 0; j < 8; ++j) {
                float o = acc2[i][j] + b2b[c0 + j];
                o = 1.f / (1.f + expf(-o));
                float rv = As[(ty * 2 + i) * LDA + c0 + j] + o;
                g_r[(size_t)row * HH + c0 + j] = rv;
                s[j]  += rv;
                s2[j] += rv * rv;
            }
        }
    }
    #pragma unroll
    for (int j = 0; j < 8; ++j) {
        atomicAdd(&g_sum[c0 + j], s[j]);
        atomicAdd(&g_sq[c0 + j],  s2[j]);
    }
}

// ---------------- BatchNorm (training-mode batch stats) -------------------
__global__ void k_bn(const float* __restrict__ gamma,
                     const float* __restrict__ beta, int n)
{
    const float invn = 1.f / (float)n;
    int total = n * HH;
    for (int idx = blockIdx.x * blockDim.x + threadIdx.x; idx < total;
         idx += gridDim.x * blockDim.x) {
        int j = idx & (HH - 1);
        float mu  = g_sum[j] * invn;
        float var = g_sq[j] * invn - mu * mu;
        g_h[idx] = (g_r[idx] - mu) * rsqrtf(var + EPSBN) * gamma[j] + beta[j];
    }
}

// ---------------- degree / zeroing helpers --------------------------------
__global__ void k_zero_cnt(int n)
{
    int i = blockIdx.x * blockDim.x + threadIdx.x;
    if (i < n) g_cnt[i] = 0;
}
__global__ void k_count(const int* __restrict__ dst, int E)
{
    int i = blockIdx.x * blockDim.x + threadIdx.x;
    if (i < E) atomicAdd(&g_cnt[dst[i]], 1);
}
__global__ void k_inv(int n)
{
    int i = blockIdx.x * blockDim.x + threadIdx.x;
    if (i < n) g_inv[i] = 1.f / fmaxf((float)g_cnt[i], 1.f);
}
__global__ void k_zero_layer(int nh4)   // nh4 = n*HH/4
{
    for (int i = blockIdx.x * blockDim.x + threadIdx.x; i < nh4;
         i += gridDim.x * blockDim.x)
        ((float4*)g_agg)[i] = make_float4(0.f, 0.f, 0.f, 0.f);
    int g = blockIdx.x * blockDim.x + threadIdx.x;
    if (g < HH) { g_sum[g] = 0.f; g_sq[g] = 0.f; }
}

// ---------------- final MLP: sigmoid(relu(h@Wf+bf)@Wo+bo) -----------------
__global__ __launch_bounds__(NT) void k_final(
    const float* __restrict__ Wf, const float* __restrict__ bf,
    const float* __restrict__ Wo, const float* __restrict__ bo,
    float* __restrict__ out, int n)
{
    extern __shared__ float smem[];
    float* As = smem;
    float* Ws = As + 64 * 132;
    const int tid = threadIdx.x;
    const int base = blockIdx.x * 64;

    for (int t = tid; t < 64 * 32; t += NT) {
        int row = t >> 5, j = (t & 31) << 2;
        float4 v = make_float4(0.f, 0.f, 0.f, 0.f);
        if (base + row < n) v = *(const float4*)(g_h + (size_t)(base + row) * HH + j);
        *(float4*)(As + row * 132 + j) = v;
    }

    float acc[4][8] = {};
    gemm_acc<4>(As, 132, Ws, Wf, HH, acc, tid);

    const int ty = tid >> 4, tx = tid & 15, c0 = tx * 8;
    #pragma unroll
    for (int i = 0; i < 4; ++i)
        #pragma unroll
        for (int j = 0; j < 8; ++j)
            As[(ty * 4 + i) * 132 + c0 + j] = fmaxf(acc[i][j] + bf[c0 + j], 0.f);
    __syncthreads();

    const int w = tid >> 5, lane = tid & 31;
    const float bo0 = bo[0];
    #pragma unroll
    for (int rr = 0; rr < 8; ++rr) {
        int row = w * 8 + rr;
        float sAcc = 0.f;
        #pragma unroll
        for (int q = 0; q < 4; ++q)
            sAcc += As[row * 132 + lane + 32 * q] * Wo[lane + 32 * q];
        #pragma unroll
        for (int off = 16; off; off >>= 1)
            sAcc += __shfl_xor_sync(0xffffffffu, sAcc, off);
        if (lane == 0 && base + row < n)
            out[base + row] = 1.f / (1.f + expf(-sAcc));
    }
}

// ---------------- launcher -------------------------------------------------
extern "C" void kernel_launch(void* const* d_in, const int* in_sizes, int n_in,
                              void* d_out, int out_size)
{
    const float* x    = (const float*)d_in[0];
    const float* ea   = (const float*)d_in[1];
    const int*   ei   = (const int*)  d_in[2];
    const float* W0   = (const float*)d_in[4];
    const float* b0   = (const float*)d_in[5];
    const float* W1   = (const float*)d_in[6];
    const float* b1   = (const float*)d_in[7];
    const float* W1a  = (const float*)d_in[8];
    const float* b1a  = (const float*)d_in[9];
    const float* W1b  = (const float*)d_in[10];
    const float* b1b  = (const float*)d_in[11];
    const float* W2a  = (const float*)d_in[12];
    const float* b2a  = (const float*)d_in[13];
    const float* W2b  = (const float*)d_in[14];
    const float* b2b  = (const float*)d_in[15];
    const float* gam  = (const float*)d_in[16];
    const float* bet  = (const float*)d_in[17];
    const float* Wf   = (const float*)d_in[18];
    const float* bf   = (const float*)d_in[19];
    const float* Wo   = (const float*)d_in[20];
    const float* bo   = (const float*)d_in[21];
    float* out = (float*)d_out;

    const int n = in_sizes[0] / 2;
    const int E = in_sizes[2] / 2;
    const int* srcp = ei;
    const int* dstp = ei + E;

    const int nb_n = (n + 63) / 64;
    const int nb_u = (n + 31) / 32;
    const int nb_e = (E + 63) / 64;

    const size_t SM_IN = (size_t)(64 * 132 + 2048 + 256 + 128 + 128) * 4;
    const size_t SM_P  = (size_t)(64 * 132 + 2048) * 4;
    const size_t SM_E  = (size_t)(64 * 132 + 2048 + 256 + 128 + 128) * 4 + 128 * 4;
    const size_t SM_U  = (size_t)(32 * 268 + 2048) * 4;
    const size_t SM_F  = (size_t)(64 * 132 + 2048) * 4;

    // input MLP
    k_input<<<nb_n, NT, SM_IN>>>(x, W0, b0, W1, b1, n);

    // in-degree + inverse denominator
    k_zero_cnt<<<(n + 255) / 256, 256>>>(n);
    k_count<<<(E + 255) / 256, 256>>>(dstp, E);
    k_inv<<<(n + 255) / 256, 256>>>(n);

    for (int l = 0; l < LL; ++l) {
        const float* W1a_l  = W1a + (size_t)l * 130 * 128;
        const float* W1a_t  = W1a_l + 128 * 128;       // rows 128,129
        const float* b1a_l  = b1a + (size_t)l * 128;
        const float* W1b_l  = W1b + (size_t)l * 128 * 128;
        const float* b1b_l  = b1b + (size_t)l * 128;
        const float* W2a_l  = W2a + (size_t)l * 256 * 128;
        const float* b2a_l  = b2a + (size_t)l * 128;
        const float* W2b_l  = W2b + (size_t)l * 128 * 128;
        const float* b2b_l  = b2b + (size_t)l * 128;
        const float* gam_l  = gam + (size_t)l * 128;
        const float* bet_l  = bet + (size_t)l * 128;

        k_zero_layer<<<2048, 256>>>(n * HH / 4);
        k_precompute<<<nb_n, NT, SM_P>>>(W1a_l, n);
        k_edge<<<nb_e, NT, SM_E>>>(ea, srcp, dstp, W1a_t, b1a_l, W1b_l, b1b_l, E);
        k_update<<<nb_u, NT, SM_U>>>(W2a_l, b2a_l, W2b_l, b2b_l, n);
        k_bn<<<1024, 256>>>(gam_l, bet_l, n);
    }

    k_final<<<nb_n, NT, SM_F>>>(Wf, bf, Wo, bo, out, n);
}

// round 2
// speedup vs baseline: 1.4806x; 1.4806x over previous
#include <cuda_runtime.h>
#include <math.h>

// Problem constants (fixed by the reference)
#define NN 50000
#define EE 800000
#define HH 128
#define LL 3
#define NT 256
#define EPSBN 1e-5f

// ---------------- scratch (static device globals; no allocation) ----------
__device__ float g_h[NN * HH];      // node features
__device__ float g_p[NN * HH];      // P = h @ W1a_top
__device__ float g_agg[NN * HH];    // edge aggregation (sums)
__device__ float g_r[NN * HH];      // residual pre-BN
__device__ float g_inv[NN];         // 1 / max(indeg, 1)
__device__ int   g_cnt[NN];         // in-degree
__device__ float g_sum[LL * HH];    // BN column sums (per layer slot)
__device__ float g_sq[LL * HH];     // BN column sum-of-squares (per layer)

// ---------------- shared tiled GEMM core (streamed W) ----------------------
template<int RPT>
__device__ __forceinline__ void gemm_acc(const float* As, int lda, float* Ws,
                                         const float* __restrict__ Wg, int K,
                                         float acc[RPT][8], int tid)
{
    const int ty = tid >> 4, tx = tid & 15;
    for (int kc = 0; kc < K; kc += 16) {
        __syncthreads();
        for (int t = tid; t < 512; t += NT) {
            int kk = t >> 5, j4 = (t & 31) << 2;
            *(float4*)(Ws + kk * HH + j4) =
                *(const float4*)(Wg + (size_t)(kc + kk) * HH + j4);
        }
        __syncthreads();
        #pragma unroll
        for (int k = 0; k < 16; ++k) {
            float a[RPT];
            #pragma unroll
            for (int i = 0; i < RPT; ++i) a[i] = As[(ty * RPT + i) * lda + kc + k];
            float4 b0 = *(const float4*)(Ws + k * HH + tx * 8);
            float4 b1 = *(const float4*)(Ws + k * HH + tx * 8 + 4);
            float bb[8] = {b0.x, b0.y, b0.z, b0.w, b1.x, b1.y, b1.z, b1.w};
            #pragma unroll
            for (int i = 0; i < RPT; ++i)
                #pragma unroll
                for (int j = 0; j < 8; ++j)
                    acc[i][j] = fmaf(a[i], bb[j], acc[i][j]);
        }
    }
    __syncthreads();
}

// ---------------- input MLP: h = relu(relu(x@W0+b0)@W1+b1) ----------------
__global__ __launch_bounds__(NT) void k_input(
    const float* __restrict__ x,
    const float* __restrict__ W0, const float* __restrict__ b0,
    const float* __restrict__ W1, const float* __restrict__ b1, int n)
{
    extern __shared__ float smem[];
    float* As  = smem;
    float* Ws  = As + 64 * 132;
    float* w0s = Ws + 2048;
    float* b0s = w0s + 256;
    float* xs  = b0s + 128;
    const int tid = threadIdx.x;
    const int base = blockIdx.x * 64;

    for (int t = tid; t < 256; t += NT) w0s[t] = W0[t];
    for (int t = tid; t < 128; t += NT) b0s[t] = b0[t];
    if (tid < 128) {
        int row = tid >> 1;
        xs[tid] = (base + row < n) ? x[(size_t)(base + row) * 2 + (tid & 1)] : 0.f;
    }
    __syncthreads();

    for (int t = tid; t < 64 * 32; t += NT) {
        int row = t >> 5, j = (t & 31) << 2;
        float x0 = xs[row * 2], x1 = xs[row * 2 + 1];
        float4 v;
        v.x = fmaxf(fmaf(x0, w0s[j + 0], fmaf(x1, w0s[128 + j + 0], b0s[j + 0])), 0.f);
        v.y = fmaxf(fmaf(x0, w0s[j + 1], fmaf(x1, w0s[128 + j + 1], b0s[j + 1])), 0.f);
        v.z = fmaxf(fmaf(x0, w0s[j + 2], fmaf(x1, w0s[128 + j + 2], b0s[j + 2])), 0.f);
        v.w = fmaxf(fmaf(x0, w0s[j + 3], fmaf(x1, w0s[128 + j + 3], b0s[j + 3])), 0.f);
        *(float4*)(As + row * 132 + j) = v;
    }

    float acc[4][8] = {};
    gemm_acc<4>(As, 132, Ws, W1, HH, acc, tid);

    const int ty = tid >> 4, tx = tid & 15, c0 = tx * 8;
    #pragma unroll
    for (int i = 0; i < 4; ++i) {
        int row = base + ty * 4 + i;
        if (row < n) {
            #pragma unroll
            for (int j = 0; j < 8; ++j)
                g_h[(size_t)row * HH + c0 + j] = fmaxf(acc[i][j] + b1[c0 + j], 0.f);
        }
    }
}

// ---------------- P = h @ W1a_top --------------------------------------
__global__ __launch_bounds__(NT) void k_precompute(
    const float* __restrict__ W, int n)
{
    extern __shared__ float smem[];
    float* As = smem;
    float* Ws = As + 64 * 132;
    const int tid = threadIdx.x;
    const int base = blockIdx.x * 64;

    for (int t = tid; t < 64 * 32; t += NT) {
        int row = t >> 5, j = (t & 31) << 2;
        float4 v = make_float4(0.f, 0.f, 0.f, 0.f);
        if (base + row < n) v = *(const float4*)(g_h + (size_t)(base + row) * HH + j);
        *(float4*)(As + row * 132 + j) = v;
    }

    float acc[4][8] = {};
    gemm_acc<4>(As, 132, Ws, W, HH, acc, tid);

    const int ty = tid >> 4, tx = tid & 15, c0 = tx * 8;
    #pragma unroll
    for (int i = 0; i < 4; ++i) {
        int row = base + ty * 4 + i;
        if (row < n) {
            #pragma unroll
            for (int j = 0; j < 8; ++j)
                g_p[(size_t)row * HH + c0 + j] = acc[i][j];
        }
    }
}

// ---------------- edge kernel v2: W resident in smem, barrier-free k-loop --
__global__ __launch_bounds__(NT) void k_edge(
    const float* __restrict__ ea,
    const int* __restrict__ src, const int* __restrict__ dst,
    const float* __restrict__ Wtail,   // rows 128,129 of W1a[l]
    const float* __restrict__ b1a,
    const float* __restrict__ W1b, const float* __restrict__ b1b,
    int E, int ntiles)
{
    extern __shared__ float smem[];
    float* Wb  = smem;                 // 128*128
    float* wt  = Wb + 16384;           // 2*128
    float* bs  = wt + 256;             // 128 (b1a)
    float* b2s = bs + 128;             // 128 (b1b)
    float* As  = b2s + 128;            // 64*132
    float* eas = As + 64 * 132;        // 128
    int*   sd  = (int*)(eas + 128);    // 128 (src 64 | dst 64)
    const int tid = threadIdx.x;
    const int ty = tid >> 4, tx = tid & 15, c0 = tx * 8;

    // stage W + params once per block
    for (int t = tid; t < 4096; t += NT)
        ((float4*)Wb)[t] = ((const float4*)W1b)[t];
    for (int t = tid; t < 256; t += NT) wt[t] = Wtail[t];
    if (tid < 128) { bs[tid] = b1a[tid]; b2s[tid] = b1b[tid]; }

    for (int tile = blockIdx.x; tile < ntiles; tile += gridDim.x) {
        const int e0 = tile * 64;
        __syncthreads();   // protect sd/eas/As from previous iter (and W init)
        if (tid < 64) {
            int e = e0 + tid;
            if (e < E) {
                sd[tid]      = src[e];
                sd[64 + tid] = dst[e];
                eas[2 * tid]     = ea[(size_t)e * 2];
                eas[2 * tid + 1] = ea[(size_t)e * 2 + 1];
            } else {
                sd[tid] = 0; sd[64 + tid] = -1;
                eas[2 * tid] = 0.f; eas[2 * tid + 1] = 0.f;
            }
        }
        __syncthreads();

        // gather P rows + rank-2 + bias + ReLU  => message tile in As
        for (int t = tid; t < 64 * 32; t += NT) {
            int row = t >> 5, j = (t & 31) << 2;
            const float4 p = *(const float4*)(g_p + (size_t)sd[row] * HH + j);
            float ev0 = eas[2 * row], ev1 = eas[2 * row + 1];
            float4 m;
            m.x = fmaxf(fmaf(ev0, wt[j + 0], fmaf(ev1, wt[128 + j + 0], p.x + bs[j + 0])), 0.f);
            m.y = fmaxf(fmaf(ev0, wt[j + 1], fmaf(ev1, wt[128 + j + 1], p.y + bs[j + 1])), 0.f);
            m.z = fmaxf(fmaf(ev0, wt[j + 2], fmaf(ev1, wt[128 + j + 2], p.z + bs[j + 2])), 0.f);
            m.w = fmaxf(fmaf(ev0, wt[j + 3], fmaf(ev1, wt[128 + j + 3], p.w + bs[j + 3])), 0.f);
            *(float4*)(As + row * 132 + j) = m;
        }
        __syncthreads();

        // barrier-free 128-deep GEMM: acc = m @ W1b (W in smem)
        float acc[4][8] = {};
        #pragma unroll 8
        for (int k = 0; k < HH; ++k) {
            float a0 = As[(ty * 4 + 0) * 132 + k];
            float a1 = As[(ty * 4 + 1) * 132 + k];
            float a2 = As[(ty * 4 + 2) * 132 + k];
            float a3 = As[(ty * 4 + 3) * 132 + k];
            float4 w0 = *(const float4*)(Wb + k * HH + c0);
            float4 w1 = *(const float4*)(Wb + k * HH + c0 + 4);
            float bb[8] = {w0.x, w0.y, w0.z, w0.w, w1.x, w1.y, w1.z, w1.w};
            #pragma unroll
            for (int j = 0; j < 8; ++j) {
                acc[0][j] = fmaf(a0, bb[j], acc[0][j]);
                acc[1][j] = fmaf(a1, bb[j], acc[1][j]);
                acc[2][j] = fmaf(a2, bb[j], acc[2][j]);
                acc[3][j] = fmaf(a3, bb[j], acc[3][j]);
            }
        }

        // bias + ReLU + vectorized reduction scatter
        #pragma unroll
        for (int i = 0; i < 4; ++i) {
            int d = sd[64 + ty * 4 + i];
            if (d >= 0) {
                float* ab = g_agg + (size_t)d * HH + c0;
                float v0 = fmaxf(acc[i][0] + b2s[c0 + 0], 0.f);
                float v1 = fmaxf(acc[i][1] + b2s[c0 + 1], 0.f);
                float v2 = fmaxf(acc[i][2] + b2s[c0 + 2], 0.f);
                float v3 = fmaxf(acc[i][3] + b2s[c0 + 3], 0.f);
                float v4 = fmaxf(acc[i][4] + b2s[c0 + 4], 0.f);
                float v5 = fmaxf(acc[i][5] + b2s[c0 + 5], 0.f);
                float v6 = fmaxf(acc[i][6] + b2s[c0 + 6], 0.f);
                float v7 = fmaxf(acc[i][7] + b2s[c0 + 7], 0.f);
                asm volatile("red.global.add.v4.f32 [%0], {%1,%2,%3,%4};"
                             :: "l"(ab), "f"(v0), "f"(v1), "f"(v2), "f"(v3)
                             : "memory");
                asm volatile("red.global.add.v4.f32 [%0], {%1,%2,%3,%4};"
                             :: "l"(ab + 4), "f"(v4), "f"(v5), "f"(v6), "f"(v7)
                             : "memory");
            }
        }
    }
}

// ---------------- node update --------------------------------------------
__global__ __launch_bounds__(NT) void k_update(
    const float* __restrict__ W2a, const float* __restrict__ b2a,
    const float* __restrict__ W2b, const float* __restrict__ b2b,
    int l, int n)
{
    extern __shared__ float smem[];
    const int LDA = 268;
    float* As = smem;              // 32*268
    float* Ws = As + 32 * LDA;     // 16*128
    const int tid = threadIdx.x;
    const int base = blockIdx.x * 32;

    for (int t = tid; t < 32 * 32; t += NT) {
        int row = t >> 5, j = (t & 31) << 2;
        float4 hv = make_float4(0.f, 0.f, 0.f, 0.f);
        float4 av = hv;
        if (base + row < n) {
            hv = *(const float4*)(g_h + (size_t)(base + row) * HH + j);
            av = *(const float4*)(g_agg + (size_t)(base + row) * HH + j);
            float iv = g_inv[base + row];
            av.x *= iv; av.y *= iv; av.z *= iv; av.w *= iv;
        }
        *(float4*)(As + row * LDA + j) = hv;
        *(float4*)(As + row * LDA + 128 + j) = av;
    }

    float acc[2][8] = {};
    gemm_acc<2>(As, LDA, Ws, W2a, 2 * HH, acc, tid);

    const int ty = tid >> 4, tx = tid & 15, c0 = tx * 8;
    #pragma unroll
    for (int i = 0; i < 2; ++i) {
        int row = ty * 2 + i;
        #pragma unroll
        for (int j = 0; j < 8; ++j)
            As[row * LDA + 128 + c0 + j] = fmaxf(acc[i][j] + b2a[c0 + j], 0.f);
    }

    float acc2[2][8] = {};
    gemm_acc<2>(As + 128, LDA, Ws, W2b, HH, acc2, tid);

    float s[8] = {}, s2[8] = {};
    #pragma unroll
    for (int i = 0; i < 2; ++i) {
        int row = base + ty * 2 + i;
        if (row < n) {
            #pragma unroll
            for (int j = 0; j < 8; ++j) {
                float o = acc2[i][j] + b2b[c0 + j];
                o = 1.f / (1.f + expf(-o));
                float rv = As[(ty * 2 + i) * LDA + c0 + j] + o;
                g_r[(size_t)row * HH + c0 + j] = rv;
                s[j]  += rv;
                s2[j] += rv * rv;
            }
        }
    }
    #pragma unroll
    for (int j = 0; j < 8; ++j) {
        atomicAdd(&g_sum[l * HH + c0 + j], s[j]);
        atomicAdd(&g_sq[l * HH + c0 + j],  s2[j]);
    }
}

// ---------------- BatchNorm (+ zero agg for next layer) -------------------
__global__ void k_bn(const float* __restrict__ gamma,
                     const float* __restrict__ beta, int l, int n)
{
    const float invn = 1.f / (float)n;
    int total = n * HH;
    for (int idx = blockIdx.x * blockDim.x + threadIdx.x; idx < total;
         idx += gridDim.x * blockDim.x) {
        int j = idx & (HH - 1);
        float mu  = g_sum[l * HH + j] * invn;
        float var = g_sq[l * HH + j] * invn - mu * mu;
        g_h[idx] = (g_r[idx] - mu) * rsqrtf(var + EPSBN) * gamma[j] + beta[j];
        g_agg[idx] = 0.f;   // ready for next layer's scatter
    }
}

// ---------------- degree / init helpers ------------------------------------
__global__ void k_zero_cnt(int n)
{
    int i = blockIdx.x * blockDim.x + threadIdx.x;
    if (i < n) g_cnt[i] = 0;
}
__global__ void k_count(const int* __restrict__ dst, int E)
{
    int i = blockIdx.x * blockDim.x + threadIdx.x;
    if (i < E) atomicAdd(&g_cnt[dst[i]], 1);
}
// inv-degree + zero g_agg + zero all BN accumulators
__global__ void k_inv(int n)
{
    int total = n * HH;
    for (int i = blockIdx.x * blockDim.x + threadIdx.x; i < total;
         i += gridDim.x * blockDim.x) {
        g_agg[i] = 0.f;
        if (i < n) g_inv[i] = 1.f / fmaxf((float)g_cnt[i], 1.f);
        if (i < LL * HH) { g_sum[i] = 0.f; g_sq[i] = 0.f; }
    }
}

// ---------------- final MLP: sigmoid(relu(h@Wf+bf)@Wo+bo) -----------------
__global__ __launch_bounds__(NT) void k_final(
    const float* __restrict__ Wf, const float* __restrict__ bf,
    const float* __restrict__ Wo, const float* __restrict__ bo,
    float* __restrict__ out, int n)
{
    extern __shared__ float smem[];
    float* As = smem;
    float* Ws = As + 64 * 132;
    const int tid = threadIdx.x;
    const int base = blockIdx.x * 64;

    for (int t = tid; t < 64 * 32; t += NT) {
        int row = t >> 5, j = (t & 31) << 2;
        float4 v = make_float4(0.f, 0.f, 0.f, 0.f);
        if (base + row < n) v = *(const float4*)(g_h + (size_t)(base + row) * HH + j);
        *(float4*)(As + row * 132 + j) = v;
    }

    float acc[4][8] = {};
    gemm_acc<4>(As, 132, Ws, Wf, HH, acc, tid);

    const int ty = tid >> 4, tx = tid & 15, c0 = tx * 8;
    #pragma unroll
    for (int i = 0; i < 4; ++i)
        #pragma unroll
        for (int j = 0; j < 8; ++j)
            As[(ty * 4 + i) * 132 + c0 + j] = fmaxf(acc[i][j] + bf[c0 + j], 0.f);
    __syncthreads();

    const int w = tid >> 5, lane = tid & 31;
    #pragma unroll
    for (int rr = 0; rr < 8; ++rr) {
        int row = w * 8 + rr;
        float sAcc = 0.f;
        #pragma unroll
        for (int q = 0; q < 4; ++q)
            sAcc += As[row * 132 + lane + 32 * q] * Wo[lane + 32 * q];
        #pragma unroll
        for (int off = 16; off; off >>= 1)
            sAcc += __shfl_xor_sync(0xffffffffu, sAcc, off);
        if (lane == 0 && base + row < n)
            out[base + row] = 1.f / (1.f + expf(-sAcc));
    }
}

// ---------------- launcher -------------------------------------------------
extern "C" void kernel_launch(void* const* d_in, const int* in_sizes, int n_in,
                              void* d_out, int out_size)
{
    const float* x    = (const float*)d_in[0];
    const float* ea   = (const float*)d_in[1];
    const int*   ei   = (const int*)  d_in[2];
    const float* W0   = (const float*)d_in[4];
    const float* b0   = (const float*)d_in[5];
    const float* W1   = (const float*)d_in[6];
    const float* b1   = (const float*)d_in[7];
    const float* W1a  = (const float*)d_in[8];
    const float* b1a  = (const float*)d_in[9];
    const float* W1b  = (const float*)d_in[10];
    const float* b1b  = (const float*)d_in[11];
    const float* W2a  = (const float*)d_in[12];
    const float* b2a  = (const float*)d_in[13];
    const float* W2b  = (const float*)d_in[14];
    const float* b2b  = (const float*)d_in[15];
    const float* gam  = (const float*)d_in[16];
    const float* bet  = (const float*)d_in[17];
    const float* Wf   = (const float*)d_in[18];
    const float* bf   = (const float*)d_in[19];
    const float* Wo   = (const float*)d_in[20];
    const float* bo   = (const float*)d_in[21];
    float* out = (float*)d_out;

    const int n = in_sizes[0] / 2;
    const int E = in_sizes[2] / 2;
    const int* srcp = ei;
    const int* dstp = ei + E;

    const int nb_n   = (n + 63) / 64;
    const int nb_u   = (n + 31) / 32;
    const int ntiles = (E + 63) / 64;
    const int gE     = 296;   // 2 blocks/SM x 148 SMs, persistent

    const size_t SM_IN = (size_t)(64 * 132 + 2048 + 256 + 128 + 128) * 4;
    const size_t SM_P  = (size_t)(64 * 132 + 2048) * 4;
    const size_t SM_E  = (size_t)(16384 + 256 + 128 + 128 + 64 * 132 + 128) * 4
                         + 128 * 4;                       // 102400 B
    const size_t SM_U  = (size_t)(32 * 268 + 2048) * 4;
    const size_t SM_F  = (size_t)(64 * 132 + 2048) * 4;

    // opt in to >48KB dynamic smem for the edge kernel (host-side, capture-safe)
    cudaFuncSetAttribute(k_edge, cudaFuncAttributeMaxDynamicSharedMemorySize,
                         (int)SM_E);

    // input MLP
    k_input<<<nb_n, NT, SM_IN>>>(x, W0, b0, W1, b1, n);

    // in-degree + inverse denominator + zero agg/BN accumulators
    k_zero_cnt<<<(n + 255) / 256, 256>>>(n);
    k_count<<<(E + 255) / 256, 256>>>(dstp, E);
    k_inv<<<1024, 256>>>(n);

    for (int l = 0; l < LL; ++l) {
        const float* W1a_l  = W1a + (size_t)l * 130 * 128;
        const float* W1a_t  = W1a_l + 128 * 128;       // rows 128,129
        const float* b1a_l  = b1a + (size_t)l * 128;
        const float* W1b_l  = W1b + (size_t)l * 128 * 128;
        const float* b1b_l  = b1b + (size_t)l * 128;
        const float* W2a_l  = W2a + (size_t)l * 256 * 128;
        const float* b2a_l  = b2a + (size_t)l * 128;
        const float* W2b_l  = W2b + (size_t)l * 128 * 128;
        const float* b2b_l  = b2b + (size_t)l * 128;
        const float* gam_l  = gam + (size_t)l * 128;
        const float* bet_l  = bet + (size_t)l * 128;

        k_precompute<<<nb_n, NT, SM_P>>>(W1a_l, n);
        k_edge<<<gE, NT, SM_E>>>(ea, srcp, dstp, W1a_t, b1a_l, W1b_l, b1b_l,
                                 E, ntiles);
        k_update<<<nb_u, NT, SM_U>>>(W2a_l, b2a_l, W2b_l, b2b_l, l, n);
        k_bn<<<1024, 256>>>(gam_l, bet_l, l, n);
    }

    k_final<<<nb_n, NT, SM_F>>>(Wf, bf, Wo, bo, out, n);
}

// round 3
// speedup vs baseline: 2.0280x; 1.3697x over previous
#include <cuda_runtime.h>
#include <math.h>
#include <stdint.h>

#define NN 50000
#define EE 800000
#define HH 128
#define LL 3
#define NT 256
#define EPSBN 1e-5f

// ---------------- scratch ---------------------------------------------------
__device__ float g_h[NN * HH];
__device__ float g_p[NN * HH];
__device__ float g_agg[NN * HH];
__device__ float g_r[NN * HH];
__device__ float g_inv[NN];
__device__ int   g_cnt[NN];
__device__ float g_sum[LL * HH];
__device__ float g_sq[LL * HH];

// ---------------- tf32 helpers ---------------------------------------------
__device__ __forceinline__ unsigned f2tf32(float f) {
    unsigned u;
    asm("cvt.rna.tf32.f32 %0, %1;" : "=r"(u) : "f"(f));
    return u;
}
__device__ __forceinline__ void mma8(float acc[4], const uint4& a,
                                     unsigned b0, unsigned b1) {
    asm volatile(
        "mma.sync.aligned.m16n8k8.row.col.f32.tf32.tf32.f32 "
        "{%0,%1,%2,%3},{%4,%5,%6,%7},{%8,%9},{%0,%1,%2,%3};\n"
        : "+f"(acc[0]), "+f"(acc[1]), "+f"(acc[2]), "+f"(acc[3])
        : "r"(a.x), "r"(a.y), "r"(a.z), "r"(a.w), "r"(b0), "r"(b1));
}

// ---------------- streamed-W fp32 GEMM core (small kernels) -----------------
template<int RPT>
__device__ __forceinline__ void gemm_acc(const float* As, int lda, float* Ws,
                                         const float* __restrict__ Wg, int K,
                                         float acc[RPT][8], int tid)
{
    const int ty = tid >> 4, tx = tid & 15;
    for (int kc = 0; kc < K; kc += 16) {
        __syncthreads();
        for (int t = tid; t < 512; t += NT) {
            int kk = t >> 5, j4 = (t & 31) << 2;
            *(float4*)(Ws + kk * HH + j4) =
                *(const float4*)(Wg + (size_t)(kc + kk) * HH + j4);
        }
        __syncthreads();
        #pragma unroll
        for (int k = 0; k < 16; ++k) {
            float a[RPT];
            #pragma unroll
            for (int i = 0; i < RPT; ++i) a[i] = As[(ty * RPT + i) * lda + kc + k];
            float4 b0 = *(const float4*)(Ws + k * HH + tx * 8);
            float4 b1 = *(const float4*)(Ws + k * HH + tx * 8 + 4);
            float bb[8] = {b0.x, b0.y, b0.z, b0.w, b1.x, b1.y, b1.z, b1.w};
            #pragma unroll
            for (int i = 0; i < RPT; ++i)
                #pragma unroll
                for (int j = 0; j < 8; ++j)
                    acc[i][j] = fmaf(a[i], bb[j], acc[i][j]);
        }
    }
    __syncthreads();
}

// ---------------- input MLP --------------------------------------------------
__global__ __launch_bounds__(NT) void k_input(
    const float* __restrict__ x,
    const float* __restrict__ W0, const float* __restrict__ b0,
    const float* __restrict__ W1, const float* __restrict__ b1, int n)
{
    extern __shared__ float smem[];
    float* As  = smem;
    float* Ws  = As + 64 * 132;
    float* w0s = Ws + 2048;
    float* b0s = w0s + 256;
    float* xs  = b0s + 128;
    const int tid = threadIdx.x;
    const int base = blockIdx.x * 64;

    for (int t = tid; t < 256; t += NT) w0s[t] = W0[t];
    for (int t = tid; t < 128; t += NT) b0s[t] = b0[t];
    if (tid < 128) {
        int row = tid >> 1;
        xs[tid] = (base + row < n) ? x[(size_t)(base + row) * 2 + (tid & 1)] : 0.f;
    }
    __syncthreads();

    for (int t = tid; t < 64 * 32; t += NT) {
        int row = t >> 5, j = (t & 31) << 2;
        float x0 = xs[row * 2], x1 = xs[row * 2 + 1];
        float4 v;
        v.x = fmaxf(fmaf(x0, w0s[j + 0], fmaf(x1, w0s[128 + j + 0], b0s[j + 0])), 0.f);
        v.y = fmaxf(fmaf(x0, w0s[j + 1], fmaf(x1, w0s[128 + j + 1], b0s[j + 1])), 0.f);
        v.z = fmaxf(fmaf(x0, w0s[j + 2], fmaf(x1, w0s[128 + j + 2], b0s[j + 2])), 0.f);
        v.w = fmaxf(fmaf(x0, w0s[j + 3], fmaf(x1, w0s[128 + j + 3], b0s[j + 3])), 0.f);
        *(float4*)(As + row * 132 + j) = v;
    }

    float acc[4][8] = {};
    gemm_acc<4>(As, 132, Ws, W1, HH, acc, tid);

    const int ty = tid >> 4, tx = tid & 15, c0 = tx * 8;
    #pragma unroll
    for (int i = 0; i < 4; ++i) {
        int row = base + ty * 4 + i;
        if (row < n) {
            #pragma unroll
            for (int j = 0; j < 8; ++j)
                g_h[(size_t)row * HH + c0 + j] = fmaxf(acc[i][j] + b1[c0 + j], 0.f);
        }
    }
}

// ---------------- P = h @ W1a_top : W-resident persistent fp32 --------------
__global__ void __launch_bounds__(NT, 2) k_precompute(
    const float* __restrict__ W, int n, int ntiles)
{
    extern __shared__ float smem[];
    float* Wb = smem;              // 128*128
    float* As = Wb + 16384;        // 64*132
    const int tid = threadIdx.x;
    const int ty = tid >> 4, tx = tid & 15, c0 = tx * 8;

    for (int t = tid; t < 4096; t += NT)
        ((float4*)Wb)[t] = ((const float4*)W)[t];

    for (int tile = blockIdx.x; tile < ntiles; tile += gridDim.x) {
        const int base = tile * 64;
        __syncthreads();
        for (int t = tid; t < 2048; t += NT) {
            int row = t >> 5, j = (t & 31) << 2;
            float4 v = make_float4(0.f, 0.f, 0.f, 0.f);
            if (base + row < n)
                v = *(const float4*)(g_h + (size_t)(base + row) * HH + j);
            *(float4*)(As + row * 132 + j) = v;
        }
        __syncthreads();

        float acc[4][8] = {};
        #pragma unroll 8
        for (int k = 0; k < HH; ++k) {
            float a0 = As[(ty * 4 + 0) * 132 + k];
            float a1 = As[(ty * 4 + 1) * 132 + k];
            float a2 = As[(ty * 4 + 2) * 132 + k];
            float a3 = As[(ty * 4 + 3) * 132 + k];
            float4 w0 = *(const float4*)(Wb + k * HH + c0);
            float4 w1 = *(const float4*)(Wb + k * HH + c0 + 4);
            float bb[8] = {w0.x, w0.y, w0.z, w0.w, w1.x, w1.y, w1.z, w1.w};
            #pragma unroll
            for (int j = 0; j < 8; ++j) {
                acc[0][j] = fmaf(a0, bb[j], acc[0][j]);
                acc[1][j] = fmaf(a1, bb[j], acc[1][j]);
                acc[2][j] = fmaf(a2, bb[j], acc[2][j]);
                acc[3][j] = fmaf(a3, bb[j], acc[3][j]);
            }
        }
        #pragma unroll
        for (int i = 0; i < 4; ++i) {
            int row = base + ty * 4 + i;
            if (row < n) {
                #pragma unroll
                for (int j = 0; j < 8; ++j)
                    g_p[(size_t)row * HH + c0 + j] = acc[i][j];
            }
        }
    }
}

// ---------------- edge kernel v3: TF32 tensor cores -------------------------
// tile = 64 edges x 128 cols, K=128.  8 warps: quarter q = rows q*16..+16,
// half h = cols h*64..+64.  Per warp: 16 k-steps x 8 n-tiles of m16n8k8.
__global__ void __launch_bounds__(NT, 2) k_edge(
    const float* __restrict__ ea,
    const int* __restrict__ src, const int* __restrict__ dst,
    const float* __restrict__ Wtail,
    const float* __restrict__ b1a,
    const float* __restrict__ W1b, const float* __restrict__ b1b,
    int E, int ntiles)
{
    extern __shared__ float smem[];
    float* Wf  = smem;                 // 128 groups * 132 (tf32 fragments)
    float* Af  = Wf + 128 * 132;       // 64 groups * 132 (A fragments / D tile)
    float* wt  = Af + 64 * 132;        // 2*128
    float* bs  = wt + 256;             // b1a
    float* b2s = bs + 128;             // b1b
    float* eas = b2s + 128;            // 2*64
    int*   sd  = (int*)(eas + 128);    // src 64 | dst 64

    const int tid  = threadIdx.x;
    const int lane = tid & 31, w = tid >> 5;
    const int q = w & 3, h = w >> 2;
    const int g = lane >> 2, tg = lane & 3;

    // --- stage W1b in mma-fragment order (tf32), once per block ---
    for (int i = tid; i < 128 * 132; i += NT) {
        int grp = i / 132, off = i % 132;
        if (off < 128) {
            int s = off & 3, t = off >> 2;
            int p = grp & 3, ks = (grp >> 2) & 15, hh = grp >> 6;
            int gg = t >> 2, tt = t & 3;
            int k = 8 * ks + tt + ((s & 1) ? 4 : 0);
            int n = hh * 64 + 16 * p + gg + ((s >= 2) ? 8 : 0);
            Wf[i] = __uint_as_float(f2tf32(W1b[k * 128 + n]));
        }
    }
    for (int t = tid; t < 256; t += NT) wt[t] = Wtail[t];
    if (tid < 128) { bs[tid] = b1a[tid]; b2s[tid] = b1b[tid]; }

    for (int tile = blockIdx.x; tile < ntiles; tile += gridDim.x) {
        const int e0 = tile * 64;
        __syncthreads();                           // B1: Af/sd/eas free
        if (tid < 64) {
            int e = e0 + tid;
            if (e < E) {
                sd[tid]      = src[e];
                sd[64 + tid] = dst[e];
                eas[2 * tid]     = ea[(size_t)e * 2];
                eas[2 * tid + 1] = ea[(size_t)e * 2 + 1];
            } else {
                sd[tid] = 0; sd[64 + tid] = -1;
                eas[2 * tid] = 0.f; eas[2 * tid + 1] = 0.f;
            }
        }
        __syncthreads();                           // B2: indices ready

        // producer: gather + rank-2 + bias + ReLU -> tf32 A-fragments
        for (int wi = tid; wi < 2048; wi += NT) {
            int row = wi >> 5, j = (wi & 31) << 2;
            const float4 p = *(const float4*)(g_p + (size_t)sd[row] * HH + j);
            float ev0 = eas[2 * row], ev1 = eas[2 * row + 1];
            float mv[4];
            mv[0] = fmaf(ev0, wt[j + 0], fmaf(ev1, wt[128 + j + 0], p.x + bs[j + 0]));
            mv[1] = fmaf(ev0, wt[j + 1], fmaf(ev1, wt[128 + j + 1], p.y + bs[j + 1]));
            mv[2] = fmaf(ev0, wt[j + 2], fmaf(ev1, wt[128 + j + 2], p.z + bs[j + 2]));
            mv[3] = fmaf(ev0, wt[j + 3], fmaf(ev1, wt[128 + j + 3], p.w + bs[j + 3]));
            int qq = row >> 4, r16 = row & 15, gg = r16 & 7, hi = r16 >> 3;
            int ks = j >> 3, lo4 = (j >> 2) & 1;
            int base = (qq * 16 + ks) * 132 + gg * 16 + hi + 2 * lo4;
            #pragma unroll
            for (int s = 0; s < 4; ++s)
                Af[base + s * 4] = __uint_as_float(f2tf32(fmaxf(mv[s], 0.f)));
        }
        __syncthreads();                           // B3: A fragments ready

        // tensor-core GEMM: D(16x64) per warp
        float acc[8][4] = {};
        #pragma unroll
        for (int ks = 0; ks < 16; ++ks) {
            uint4 a = *(const uint4*)(Af + (q * 16 + ks) * 132 + lane * 4);
            #pragma unroll
            for (int p = 0; p < 4; ++p) {
                uint4 b = *(const uint4*)(Wf + ((h * 16 + ks) * 4 + p) * 132 + lane * 4);
                mma8(acc[2 * p],     a, b.x, b.y);
                mma8(acc[2 * p + 1], a, b.z, b.w);
            }
        }
        __syncthreads();                           // B4: Af reads done -> reuse as D

        #pragma unroll
        for (int nt = 0; nt < 8; ++nt) {
            int col = h * 64 + 8 * nt + 2 * tg;
            *(float2*)(Af + (q * 16 + g) * 132 + col)     = make_float2(acc[nt][0], acc[nt][1]);
            *(float2*)(Af + (q * 16 + g + 8) * 132 + col) = make_float2(acc[nt][2], acc[nt][3]);
        }
        __syncthreads();                           // B5: D tile ready

        // bias + ReLU + coalesced vector reduction scatter
        for (int wi = tid; wi < 2048; wi += NT) {
            int row = wi >> 5, j = (wi & 31) << 2;
            int d = sd[64 + row];
            if (d >= 0) {
                float4 v = *(const float4*)(Af + row * 132 + j);
                float v0 = fmaxf(v.x + b2s[j + 0], 0.f);
                float v1 = fmaxf(v.y + b2s[j + 1], 0.f);
                float v2 = fmaxf(v.z + b2s[j + 2], 0.f);
                float v3 = fmaxf(v.w + b2s[j + 3], 0.f);
                float* ab = g_agg + (size_t)d * HH + j;
                asm volatile("red.global.add.v4.f32 [%0], {%1,%2,%3,%4};"
                             :: "l"(ab), "f"(v0), "f"(v1), "f"(v2), "f"(v3)
                             : "memory");
            }
        }
    }
}

// ---------------- node update -----------------------------------------------
__global__ __launch_bounds__(NT) void k_update(
    const float* __restrict__ W2a, const float* __restrict__ b2a,
    const float* __restrict__ W2b, const float* __restrict__ b2b,
    int l, int n)
{
    extern __shared__ float smem[];
    const int LDA = 268;
    float* As = smem;
    float* Ws = As + 32 * LDA;
    const int tid = threadIdx.x;
    const int base = blockIdx.x * 32;

    for (int t = tid; t < 32 * 32; t += NT) {
        int row = t >> 5, j = (t & 31) << 2;
        float4 hv = make_float4(0.f, 0.f, 0.f, 0.f);
        float4 av = hv;
        if (base + row < n) {
            hv = *(const float4*)(g_h + (size_t)(base + row) * HH + j);
            av = *(const float4*)(g_agg + (size_t)(base + row) * HH + j);
            float iv = g_inv[base + row];
            av.x *= iv; av.y *= iv; av.z *= iv; av.w *= iv;
        }
        *(float4*)(As + row * LDA + j) = hv;
        *(float4*)(As + row * LDA + 128 + j) = av;
    }

    float acc[2][8] = {};
    gemm_acc<2>(As, LDA, Ws, W2a, 2 * HH, acc, tid);

    const int ty = tid >> 4, tx = tid & 15, c0 = tx * 8;
    #pragma unroll
    for (int i = 0; i < 2; ++i) {
        int row = ty * 2 + i;
        #pragma unroll
        for (int j = 0; j < 8; ++j)
            As[row * LDA + 128 + c0 + j] = fmaxf(acc[i][j] + b2a[c0 + j], 0.f);
    }

    float acc2[2][8] = {};
    gemm_acc<2>(As + 128, LDA, Ws, W2b, HH, acc2, tid);

    float s[8] = {}, s2[8] = {};
    #pragma unroll
    for (int i = 0; i < 2; ++i) {
        int row = base + ty * 2 + i;
        if (row < n) {
            #pragma unroll
            for (int j = 0; j < 8; ++j) {
                float o = acc2[i][j] + b2b[c0 + j];
                o = 1.f / (1.f + expf(-o));
                float rv = As[(ty * 2 + i) * LDA + c0 + j] + o;
                g_r[(size_t)row * HH + c0 + j] = rv;
                s[j]  += rv;
                s2[j] += rv * rv;
            }
        }
    }
    #pragma unroll
    for (int j = 0; j < 8; ++j) {
        atomicAdd(&g_sum[l * HH + c0 + j], s[j]);
        atomicAdd(&g_sq[l * HH + c0 + j],  s2[j]);
    }
}

// ---------------- BatchNorm (+ zero agg for next layer) ---------------------
__global__ void k_bn(const float* __restrict__ gamma,
                     const float* __restrict__ beta, int l, int n)
{
    const float invn = 1.f / (float)n;
    int total = n * HH;
    for (int idx = blockIdx.x * blockDim.x + threadIdx.x; idx < total;
         idx += gridDim.x * blockDim.x) {
        int j = idx & (HH - 1);
        float mu  = g_sum[l * HH + j] * invn;
        float var = g_sq[l * HH + j] * invn - mu * mu;
        g_h[idx] = (g_r[idx] - mu) * rsqrtf(var + EPSBN) * gamma[j] + beta[j];
        g_agg[idx] = 0.f;
    }
}

// ---------------- degree / init helpers -------------------------------------
__global__ void k_zero_cnt(int n)
{
    int i = blockIdx.x * blockDim.x + threadIdx.x;
    if (i < n) g_cnt[i] = 0;
}
__global__ void k_count(const int* __restrict__ dst, int E)
{
    int i = blockIdx.x * blockDim.x + threadIdx.x;
    if (i < E) atomicAdd(&g_cnt[dst[i]], 1);
}
__global__ void k_inv(int n)
{
    int total = n * HH;
    for (int i = blockIdx.x * blockDim.x + threadIdx.x; i < total;
         i += gridDim.x * blockDim.x) {
        g_agg[i] = 0.f;
        if (i < n) g_inv[i] = 1.f / fmaxf((float)g_cnt[i], 1.f);
        if (i < LL * HH) { g_sum[i] = 0.f; g_sq[i] = 0.f; }
    }
}

// ---------------- final MLP ---------------------------------------------------
__global__ __launch_bounds__(NT) void k_final(
    const float* __restrict__ Wf, const float* __restrict__ bf,
    const float* __restrict__ Wo, const float* __restrict__ bo,
    float* __restrict__ out, int n)
{
    extern __shared__ float smem[];
    float* As = smem;
    float* Ws = As + 64 * 132;
    const int tid = threadIdx.x;
    const int base = blockIdx.x * 64;

    for (int t = tid; t < 64 * 32; t += NT) {
        int row = t >> 5, j = (t & 31) << 2;
        float4 v = make_float4(0.f, 0.f, 0.f, 0.f);
        if (base + row < n) v = *(const float4*)(g_h + (size_t)(base + row) * HH + j);
        *(float4*)(As + row * 132 + j) = v;
    }

    float acc[4][8] = {};
    gemm_acc<4>(As, 132, Ws, Wf, HH, acc, tid);

    const int ty = tid >> 4, tx = tid & 15, c0 = tx * 8;
    #pragma unroll
    for (int i = 0; i < 4; ++i)
        #pragma unroll
        for (int j = 0; j < 8; ++j)
            As[(ty * 4 + i) * 132 + c0 + j] = fmaxf(acc[i][j] + bf[c0 + j], 0.f);
    __syncthreads();

    const int w = tid >> 5, lane = tid & 31;
    #pragma unroll
    for (int rr = 0; rr < 8; ++rr) {
        int row = w * 8 + rr;
        float sAcc = 0.f;
        #pragma unroll
        for (int qq = 0; qq < 4; ++qq)
            sAcc += As[row * 132 + lane + 32 * qq] * Wo[lane + 32 * qq];
        #pragma unroll
        for (int off = 16; off; off >>= 1)
            sAcc += __shfl_xor_sync(0xffffffffu, sAcc, off);
        if (lane == 0 && base + row < n)
            out[base + row] = 1.f / (1.f + expf(-sAcc));
    }
}

// ---------------- launcher ---------------------------------------------------
extern "C" void kernel_launch(void* const* d_in, const int* in_sizes, int n_in,
                              void* d_out, int out_size)
{
    const float* x    = (const float*)d_in[0];
    const float* ea   = (const float*)d_in[1];
    const int*   ei   = (const int*)  d_in[2];
    const float* W0   = (const float*)d_in[4];
    const float* b0   = (const float*)d_in[5];
    const float* W1   = (const float*)d_in[6];
    const float* b1   = (const float*)d_in[7];
    const float* W1a  = (const float*)d_in[8];
    const float* b1a  = (const float*)d_in[9];
    const float* W1b  = (const float*)d_in[10];
    const float* b1b  = (const float*)d_in[11];
    const float* W2a  = (const float*)d_in[12];
    const float* b2a  = (const float*)d_in[13];
    const float* W2b  = (const float*)d_in[14];
    const float* b2b  = (const float*)d_in[15];
    const float* gam  = (const float*)d_in[16];
    const float* bet  = (const float*)d_in[17];
    const float* Wf   = (const float*)d_in[18];
    const float* bf   = (const float*)d_in[19];
    const float* Wo   = (const float*)d_in[20];
    const float* bo   = (const float*)d_in[21];
    float* out = (float*)d_out;

    const int n = in_sizes[0] / 2;
    const int E = in_sizes[2] / 2;
    const int* srcp = ei;
    const int* dstp = ei + E;

    const int nb_n     = (n + 63) / 64;
    const int nb_u     = (n + 31) / 32;
    const int ntiles_e = (E + 63) / 64;
    const int gPers    = 296;   // 2 blocks/SM persistent

    const size_t SM_IN = (size_t)(64 * 132 + 2048 + 256 + 128 + 128) * 4;
    const size_t SM_P  = (size_t)(16384 + 64 * 132) * 4;                    // 99328
    const size_t SM_E  = (size_t)(128 * 132 + 64 * 132 + 256 + 128 + 128 + 128) * 4
                         + 128 * 4;                                         // 104448
    const size_t SM_U  = (size_t)(32 * 268 + 2048) * 4;
    const size_t SM_F  = (size_t)(64 * 132 + 2048) * 4;

    cudaFuncSetAttribute(k_edge, cudaFuncAttributeMaxDynamicSharedMemorySize,
                         (int)SM_E);
    cudaFuncSetAttribute(k_precompute, cudaFuncAttributeMaxDynamicSharedMemorySize,
                         (int)SM_P);

    k_input<<<nb_n, NT, SM_IN>>>(x, W0, b0, W1, b1, n);

    k_zero_cnt<<<(n + 255) / 256, 256>>>(n);
    k_count<<<(E + 255) / 256, 256>>>(dstp, E);
    k_inv<<<1024, 256>>>(n);

    const int ntiles_n = (n + 63) / 64;

    for (int l = 0; l < LL; ++l) {
        const float* W1a_l  = W1a + (size_t)l * 130 * 128;
        const float* W1a_t  = W1a_l + 128 * 128;
        const float* b1a_l  = b1a + (size_t)l * 128;
        const float* W1b_l  = W1b + (size_t)l * 128 * 128;
        const float* b1b_l  = b1b + (size_t)l * 128;
        const float* W2a_l  = W2a + (size_t)l * 256 * 128;
        const float* b2a_l  = b2a + (size_t)l * 128;
        const float* W2b_l  = W2b + (size_t)l * 128 * 128;
        const float* b2b_l  = b2b + (size_t)l * 128;
        const float* gam_l  = gam + (size_t)l * 128;
        const float* bet_l  = bet + (size_t)l * 128;

        k_precompute<<<gPers, NT, SM_P>>>(W1a_l, n, ntiles_n);
        k_edge<<<gPers, NT, SM_E>>>(ea, srcp, dstp, W1a_t, b1a_l, W1b_l, b1b_l,
                                    E, ntiles_e);
        k_update<<<nb_u, NT, SM_U>>>(W2a_l, b2a_l, W2b_l, b2b_l, l, n);
        k_bn<<<1024, 256>>>(gam_l, bet_l, l, n);
    }

    k_final<<<nb_n, NT, SM_F>>>(Wf, bf, Wo, bo, out, n);
}

// round 4
// speedup vs baseline: 5.1666x; 2.5476x over previous
#include <cuda_runtime.h>
#include <math.h>
#include <stdint.h>

#define NN 50000
#define EE 800000
#define HH 128
#define LL 3
#define NT 256
#define EPSBN 1e-5f

// ---------------- scratch ---------------------------------------------------
__device__ float g_h[NN * HH];
__device__ float g_p[NN * HH];
__device__ float g_agg[NN * HH];
__device__ float g_u[NN * HH];
__device__ float g_r[NN * HH];
__device__ int   g_cnt[NN];
__device__ float g_sum[LL * HH];
__device__ float g_sq[LL * HH];

// ---------------- tf32 helpers ----------------------------------------------
__device__ __forceinline__ unsigned f2tf32(float f) {
    unsigned u;
    asm("cvt.rna.tf32.f32 %0, %1;" : "=r"(u) : "f"(f));
    return u;
}
__device__ __forceinline__ void mma8(float acc[4], const uint4& a,
                                     unsigned b0, unsigned b1) {
    asm volatile(
        "mma.sync.aligned.m16n8k8.row.col.f32.tf32.tf32.f32 "
        "{%0,%1,%2,%3},{%4,%5,%6,%7},{%8,%9},{%0,%1,%2,%3};\n"
        : "+f"(acc[0]), "+f"(acc[1]), "+f"(acc[2]), "+f"(acc[3])
        : "r"(a.x), "r"(a.y), "r"(a.z), "r"(a.w), "r"(b0), "r"(b1));
}

// Stage a KxN(128) row-major fp32 weight into tf32 mma-fragment order.
// Group layout: grp = hh*(KS*4) + ks*4 + p ; 132 floats per group.
__device__ __forceinline__ void stage_w_frag(float* Wf, const float* __restrict__ Wg,
                                             int KS /*k-steps = K/8*/, int tid)
{
    const int total = 2 * KS * 4 * 132;
    for (int i = tid; i < total; i += NT) {
        int grp = i / 132, off = i % 132;
        if (off < 128) {
            int s = off & 3, t = off >> 2;
            int gg = t >> 2, tt = t & 3;
            int hh = grp / (KS * 4);
            int rem = grp - hh * (KS * 4);
            int ks = rem >> 2, p = rem & 3;
            int k = 8 * ks + tt + ((s & 1) ? 4 : 0);
            int n = hh * 64 + 16 * p + gg + ((s >= 2) ? 8 : 0);
            Wf[i] = __uint_as_float(f2tf32(Wg[(size_t)k * 128 + n]));
        }
    }
}

// ---------------- streamed-W fp32 GEMM core (k_input / k_final only) --------
template<int RPT>
__device__ __forceinline__ void gemm_acc(const float* As, int lda, float* Ws,
                                         const float* __restrict__ Wg, int K,
                                         float acc[RPT][8], int tid)
{
    const int ty = tid >> 4, tx = tid & 15;
    for (int kc = 0; kc < K; kc += 16) {
        __syncthreads();
        for (int t = tid; t < 512; t += NT) {
            int kk = t >> 5, j4 = (t & 31) << 2;
            *(float4*)(Ws + kk * HH + j4) =
                *(const float4*)(Wg + (size_t)(kc + kk) * HH + j4);
        }
        __syncthreads();
        #pragma unroll
        for (int k = 0; k < 16; ++k) {
            float a[RPT];
            #pragma unroll
            for (int i = 0; i < RPT; ++i) a[i] = As[(ty * RPT + i) * lda + kc + k];
            float4 b0 = *(const float4*)(Ws + k * HH + tx * 8);
            float4 b1 = *(const float4*)(Ws + k * HH + tx * 8 + 4);
            float bb[8] = {b0.x, b0.y, b0.z, b0.w, b1.x, b1.y, b1.z, b1.w};
            #pragma unroll
            for (int i = 0; i < RPT; ++i)
                #pragma unroll
                for (int j = 0; j < 8; ++j)
                    acc[i][j] = fmaf(a[i], bb[j], acc[i][j]);
        }
    }
    __syncthreads();
}

// ---------------- zero init ---------------------------------------------------
__global__ void k_zero(int n)
{
    int total = n * HH;
    for (int i = blockIdx.x * blockDim.x + threadIdx.x; i < total;
         i += gridDim.x * blockDim.x) {
        g_agg[i] = 0.f;
        if (i < n) g_cnt[i] = 0;
        if (i < LL * HH) { g_sum[i] = 0.f; g_sq[i] = 0.f; }
    }
}

// ---------------- input MLP + degree count -----------------------------------
__global__ __launch_bounds__(NT) void k_input(
    const float* __restrict__ x,
    const float* __restrict__ W0, const float* __restrict__ b0,
    const float* __restrict__ W1, const float* __restrict__ b1,
    const int* __restrict__ dst, int E, int n)
{
    extern __shared__ float smem[];
    float* As  = smem;
    float* Ws  = As + 64 * 132;
    float* w0s = Ws + 2048;
    float* b0s = w0s + 256;
    float* xs  = b0s + 128;
    const int tid = threadIdx.x;
    const int base = blockIdx.x * 64;

    // in-degree counting (independent of MLP work)
    for (int e = blockIdx.x * blockDim.x + tid; e < E; e += gridDim.x * blockDim.x)
        atomicAdd(&g_cnt[dst[e]], 1);

    for (int t = tid; t < 256; t += NT) w0s[t] = W0[t];
    for (int t = tid; t < 128; t += NT) b0s[t] = b0[t];
    if (tid < 128) {
        int row = tid >> 1;
        xs[tid] = (base + row < n) ? x[(size_t)(base + row) * 2 + (tid & 1)] : 0.f;
    }
    __syncthreads();

    for (int t = tid; t < 64 * 32; t += NT) {
        int row = t >> 5, j = (t & 31) << 2;
        float x0 = xs[row * 2], x1 = xs[row * 2 + 1];
        float4 v;
        v.x = fmaxf(fmaf(x0, w0s[j + 0], fmaf(x1, w0s[128 + j + 0], b0s[j + 0])), 0.f);
        v.y = fmaxf(fmaf(x0, w0s[j + 1], fmaf(x1, w0s[128 + j + 1], b0s[j + 1])), 0.f);
        v.z = fmaxf(fmaf(x0, w0s[j + 2], fmaf(x1, w0s[128 + j + 2], b0s[j + 2])), 0.f);
        v.w = fmaxf(fmaf(x0, w0s[j + 3], fmaf(x1, w0s[128 + j + 3], b0s[j + 3])), 0.f);
        *(float4*)(As + row * 132 + j) = v;
    }

    float acc[4][8] = {};
    gemm_acc<4>(As, 132, Ws, W1, HH, acc, tid);

    const int ty = tid >> 4, tx = tid & 15, c0 = tx * 8;
    #pragma unroll
    for (int i = 0; i < 4; ++i) {
        int row = base + ty * 4 + i;
        if (row < n) {
            #pragma unroll
            for (int j = 0; j < 8; ++j)
                g_h[(size_t)row * HH + c0 + j] = fmaxf(acc[i][j] + b1[c0 + j], 0.f);
        }
    }
}

// ---------------- P = h @ W1a_top : tensorized, W-resident -------------------
__global__ void __launch_bounds__(NT, 2) k_precompute(
    const float* __restrict__ W, int n, int ntiles)
{
    extern __shared__ float smem[];
    float* Wf = smem;               // 128*132
    float* Af = Wf + 128 * 132;     // 64*132
    const int tid  = threadIdx.x;
    const int lane = tid & 31, w = tid >> 5;
    const int q = w & 3, h = w >> 2;
    const int g = lane >> 2, tg = lane & 3;

    stage_w_frag(Wf, W, 16, tid);

    for (int tile = blockIdx.x; tile < ntiles; tile += gridDim.x) {
        const int base = tile * 64;
        __syncthreads();
        for (int wi = tid; wi < 2048; wi += NT) {
            int row = wi >> 5, j = (wi & 31) << 2;
            float4 v = make_float4(0.f, 0.f, 0.f, 0.f);
            if (base + row < n)
                v = *(const float4*)(g_h + (size_t)(base + row) * HH + j);
            float mv[4] = {v.x, v.y, v.z, v.w};
            int qq = row >> 4, r16 = row & 15, gg = r16 & 7, hi = r16 >> 3;
            int ks = j >> 3, lo4 = (j >> 2) & 1;
            int fbase = (qq * 16 + ks) * 132 + gg * 16 + hi + 2 * lo4;
            #pragma unroll
            for (int s = 0; s < 4; ++s)
                Af[fbase + s * 4] = __uint_as_float(f2tf32(mv[s]));
        }
        __syncthreads();

        float acc[8][4] = {};
        #pragma unroll
        for (int ks = 0; ks < 16; ++ks) {
            uint4 a = *(const uint4*)(Af + (q * 16 + ks) * 132 + lane * 4);
            #pragma unroll
            for (int p = 0; p < 4; ++p) {
                uint4 b = *(const uint4*)(Wf + ((h * 16 + ks) * 4 + p) * 132 + lane * 4);
                mma8(acc[2 * p],     a, b.x, b.y);
                mma8(acc[2 * p + 1], a, b.z, b.w);
            }
        }
        int r0 = base + q * 16 + g;
        #pragma unroll
        for (int nt = 0; nt < 8; ++nt) {
            int col = h * 64 + 8 * nt + 2 * tg;
            if (r0 < n)
                *(float2*)(g_p + (size_t)r0 * HH + col) = make_float2(acc[nt][0], acc[nt][1]);
            if (r0 + 8 < n)
                *(float2*)(g_p + (size_t)(r0 + 8) * HH + col) = make_float2(acc[nt][2], acc[nt][3]);
        }
    }
}

// ---------------- edge kernel: TF32 tensor cores ------------------------------
__global__ void __launch_bounds__(NT, 2) k_edge(
    const float* __restrict__ ea,
    const int* __restrict__ src, const int* __restrict__ dst,
    const float* __restrict__ Wtail,
    const float* __restrict__ b1a,
    const float* __restrict__ W1b, const float* __restrict__ b1b,
    int E, int ntiles)
{
    extern __shared__ float smem[];
    float* Wf  = smem;                 // 128*132
    float* Af  = Wf + 128 * 132;       // 64*132
    float* wt  = Af + 64 * 132;        // 2*128
    float* bs  = wt + 256;             // b1a
    float* b2s = bs + 128;             // b1b
    float* eas = b2s + 128;            // 2*64
    int*   sd  = (int*)(eas + 128);    // src 64 | dst 64

    const int tid  = threadIdx.x;
    const int lane = tid & 31, w = tid >> 5;
    const int q = w & 3, h = w >> 2;
    const int g = lane >> 2, tg = lane & 3;

    stage_w_frag(Wf, W1b, 16, tid);
    for (int t = tid; t < 256; t += NT) wt[t] = Wtail[t];
    if (tid < 128) { bs[tid] = b1a[tid]; b2s[tid] = b1b[tid]; }

    for (int tile = blockIdx.x; tile < ntiles; tile += gridDim.x) {
        const int e0 = tile * 64;
        __syncthreads();
        if (tid < 64) {
            int e = e0 + tid;
            if (e < E) {
                sd[tid]      = src[e];
                sd[64 + tid] = dst[e];
                eas[2 * tid]     = ea[(size_t)e * 2];
                eas[2 * tid + 1] = ea[(size_t)e * 2 + 1];
            } else {
                sd[tid] = 0; sd[64 + tid] = -1;
                eas[2 * tid] = 0.f; eas[2 * tid + 1] = 0.f;
            }
        }
        __syncthreads();

        for (int wi = tid; wi < 2048; wi += NT) {
            int row = wi >> 5, j = (wi & 31) << 2;
            const float4 p = *(const float4*)(g_p + (size_t)sd[row] * HH + j);
            float ev0 = eas[2 * row], ev1 = eas[2 * row + 1];
            float mv[4];
            mv[0] = fmaf(ev0, wt[j + 0], fmaf(ev1, wt[128 + j + 0], p.x + bs[j + 0]));
            mv[1] = fmaf(ev0, wt[j + 1], fmaf(ev1, wt[128 + j + 1], p.y + bs[j + 1]));
            mv[2] = fmaf(ev0, wt[j + 2], fmaf(ev1, wt[128 + j + 2], p.z + bs[j + 2]));
            mv[3] = fmaf(ev0, wt[j + 3], fmaf(ev1, wt[128 + j + 3], p.w + bs[j + 3]));
            int qq = row >> 4, r16 = row & 15, gg = r16 & 7, hi = r16 >> 3;
            int ks = j >> 3, lo4 = (j >> 2) & 1;
            int fbase = (qq * 16 + ks) * 132 + gg * 16 + hi + 2 * lo4;
            #pragma unroll
            for (int s = 0; s < 4; ++s)
                Af[fbase + s * 4] = __uint_as_float(f2tf32(fmaxf(mv[s], 0.f)));
        }
        __syncthreads();

        float acc[8][4] = {};
        #pragma unroll
        for (int ks = 0; ks < 16; ++ks) {
            uint4 a = *(const uint4*)(Af + (q * 16 + ks) * 132 + lane * 4);
            #pragma unroll
            for (int p = 0; p < 4; ++p) {
                uint4 b = *(const uint4*)(Wf + ((h * 16 + ks) * 4 + p) * 132 + lane * 4);
                mma8(acc[2 * p],     a, b.x, b.y);
                mma8(acc[2 * p + 1], a, b.z, b.w);
            }
        }
        __syncthreads();   // Af reads done -> reuse as D tile

        #pragma unroll
        for (int nt = 0; nt < 8; ++nt) {
            int col = h * 64 + 8 * nt + 2 * tg;
            *(float2*)(Af + (q * 16 + g) * 132 + col)     = make_float2(acc[nt][0], acc[nt][1]);
            *(float2*)(Af + (q * 16 + g + 8) * 132 + col) = make_float2(acc[nt][2], acc[nt][3]);
        }
        __syncthreads();

        for (int wi = tid; wi < 2048; wi += NT) {
            int row = wi >> 5, j = (wi & 31) << 2;
            int d = sd[64 + row];
            if (d >= 0) {
                float4 v = *(const float4*)(Af + row * 132 + j);
                float v0 = fmaxf(v.x + b2s[j + 0], 0.f);
                float v1 = fmaxf(v.y + b2s[j + 1], 0.f);
                float v2 = fmaxf(v.z + b2s[j + 2], 0.f);
                float v3 = fmaxf(v.w + b2s[j + 3], 0.f);
                float* ab = g_agg + (size_t)d * HH + j;
                asm volatile("red.global.add.v4.f32 [%0], {%1,%2,%3,%4};"
                             :: "l"(ab), "f"(v0), "f"(v1), "f"(v2), "f"(v3)
                             : "memory");
            }
        }
    }
}

// ---------------- update1: U = relu([h | agg/deg] @ W2a + b2a) ---------------
__global__ void __launch_bounds__(NT, 1) k_update1(
    const float* __restrict__ W2a, const float* __restrict__ b2a,
    int n, int ntiles)
{
    extern __shared__ float smem[];
    float* Wf = smem;               // 256*132 (K=256)
    float* Af = Wf + 256 * 132;     // 128*132
    float* bs = Af + 128 * 132;     // 128
    const int tid  = threadIdx.x;
    const int lane = tid & 31, w = tid >> 5;
    const int q = w & 3, h = w >> 2;
    const int g = lane >> 2, tg = lane & 3;

    stage_w_frag(Wf, W2a, 32, tid);
    if (tid < 128) bs[tid] = b2a[tid];

    for (int tile = blockIdx.x; tile < ntiles; tile += gridDim.x) {
        const int base = tile * 64;
        __syncthreads();
        // producer: A = [h | agg * invdeg], K=256, tf32 fragments
        for (int wi = tid; wi < 4096; wi += NT) {
            int row = wi >> 6, c4 = wi & 63, j = c4 << 2;
            int node = base + row;
            float mv[4] = {0.f, 0.f, 0.f, 0.f};
            if (node < n) {
                if (j < 128) {
                    float4 v = *(const float4*)(g_h + (size_t)node * HH + j);
                    mv[0] = v.x; mv[1] = v.y; mv[2] = v.z; mv[3] = v.w;
                } else {
                    float4 v = *(const float4*)(g_agg + (size_t)node * HH + (j - 128));
                    float iv = 1.f / fmaxf((float)g_cnt[node], 1.f);
                    mv[0] = v.x * iv; mv[1] = v.y * iv; mv[2] = v.z * iv; mv[3] = v.w * iv;
                }
            }
            int qq = row >> 4, r16 = row & 15, gg = r16 & 7, hi = r16 >> 3;
            int ks = j >> 3, lo4 = (j >> 2) & 1;
            int fbase = (qq * 32 + ks) * 132 + gg * 16 + hi + 2 * lo4;
            #pragma unroll
            for (int s = 0; s < 4; ++s)
                Af[fbase + s * 4] = __uint_as_float(f2tf32(mv[s]));
        }
        __syncthreads();

        float acc[8][4] = {};
        #pragma unroll
        for (int ks = 0; ks < 32; ++ks) {
            uint4 a = *(const uint4*)(Af + (q * 32 + ks) * 132 + lane * 4);
            #pragma unroll
            for (int p = 0; p < 4; ++p) {
                uint4 b = *(const uint4*)(Wf + ((h * 32 + ks) * 4 + p) * 132 + lane * 4);
                mma8(acc[2 * p],     a, b.x, b.y);
                mma8(acc[2 * p + 1], a, b.z, b.w);
            }
        }

        int r0 = base + q * 16 + g;
        #pragma unroll
        for (int nt = 0; nt < 8; ++nt) {
            int col = h * 64 + 8 * nt + 2 * tg;
            if (r0 < n)
                *(float2*)(g_u + (size_t)r0 * HH + col) =
                    make_float2(fmaxf(acc[nt][0] + bs[col], 0.f),
                                fmaxf(acc[nt][1] + bs[col + 1], 0.f));
            if (r0 + 8 < n)
                *(float2*)(g_u + (size_t)(r0 + 8) * HH + col) =
                    make_float2(fmaxf(acc[nt][2] + bs[col], 0.f),
                                fmaxf(acc[nt][3] + bs[col + 1], 0.f));
        }
    }
}

// ---------------- update2: out = sigmoid(U@W2b+b), r=h+out, BN stats ---------
__global__ void __launch_bounds__(NT, 2) k_update2(
    const float* __restrict__ W2b, const float* __restrict__ b2b,
    int l, int n, int ntiles)
{
    extern __shared__ float smem[];
    float* Wf = smem;               // 128*132
    float* Af = Wf + 128 * 132;     // 64*132 (A fragments, then D tile)
    float* bs = Af + 64 * 132;      // 128
    const int tid  = threadIdx.x;
    const int lane = tid & 31, w = tid >> 5;
    const int q = w & 3, h = w >> 2;
    const int g = lane >> 2, tg = lane & 3;

    stage_w_frag(Wf, W2b, 16, tid);
    if (tid < 128) bs[tid] = b2b[tid];

    for (int tile = blockIdx.x; tile < ntiles; tile += gridDim.x) {
        const int base = tile * 64;
        __syncthreads();
        for (int wi = tid; wi < 2048; wi += NT) {
            int row = wi >> 5, j = (wi & 31) << 2;
            float4 v = make_float4(0.f, 0.f, 0.f, 0.f);
            if (base + row < n)
                v = *(const float4*)(g_u + (size_t)(base + row) * HH + j);
            float mv[4] = {v.x, v.y, v.z, v.w};
            int qq = row >> 4, r16 = row & 15, gg = r16 & 7, hi = r16 >> 3;
            int ks = j >> 3, lo4 = (j >> 2) & 1;
            int fbase = (qq * 16 + ks) * 132 + gg * 16 + hi + 2 * lo4;
            #pragma unroll
            for (int s = 0; s < 4; ++s)
                Af[fbase + s * 4] = __uint_as_float(f2tf32(mv[s]));
        }
        __syncthreads();

        float acc[8][4] = {};
        #pragma unroll
        for (int ks = 0; ks < 16; ++ks) {
            uint4 a = *(const uint4*)(Af + (q * 16 + ks) * 132 + lane * 4);
            #pragma unroll
            for (int p = 0; p < 4; ++p) {
                uint4 b = *(const uint4*)(Wf + ((h * 16 + ks) * 4 + p) * 132 + lane * 4);
                mma8(acc[2 * p],     a, b.x, b.y);
                mma8(acc[2 * p + 1], a, b.z, b.w);
            }
        }
        __syncthreads();   // Af reads done -> reuse as r tile

        int r0 = base + q * 16 + g;
        #pragma unroll
        for (int nt = 0; nt < 8; ++nt) {
            int col = h * 64 + 8 * nt + 2 * tg;
            float2 rv0 = make_float2(0.f, 0.f), rv1 = make_float2(0.f, 0.f);
            if (r0 < n) {
                float2 hv = *(const float2*)(g_h + (size_t)r0 * HH + col);
                rv0.x = hv.x + 1.f / (1.f + expf(-(acc[nt][0] + bs[col])));
                rv0.y = hv.y + 1.f / (1.f + expf(-(acc[nt][1] + bs[col + 1])));
            }
            if (r0 + 8 < n) {
                float2 hv = *(const float2*)(g_h + (size_t)(r0 + 8) * HH + col);
                rv1.x = hv.x + 1.f / (1.f + expf(-(acc[nt][2] + bs[col])));
                rv1.y = hv.y + 1.f / (1.f + expf(-(acc[nt][3] + bs[col + 1])));
            }
            *(float2*)(Af + (q * 16 + g) * 132 + col)     = rv0;
            *(float2*)(Af + (q * 16 + g + 8) * 132 + col) = rv1;
        }
        __syncthreads();

        // write r + BN column partial sums
        for (int wi = tid; wi < 2048; wi += NT) {
            int row = wi >> 5, j = (wi & 31) << 2;
            if (base + row < n) {
                float4 v = *(const float4*)(Af + row * 132 + j);
                *(float4*)(g_r + (size_t)(base + row) * HH + j) = v;
            }
        }
        {
            int c = tid & 127, half = tid >> 7;
            float s = 0.f, s2 = 0.f;
            #pragma unroll 8
            for (int r = half * 32; r < half * 32 + 32; ++r) {
                float v = Af[r * 132 + c];
                s += v; s2 += v * v;
            }
            atomicAdd(&g_sum[l * HH + c], s);
            atomicAdd(&g_sq[l * HH + c],  s2);
        }
    }
}

// ---------------- BatchNorm (+ zero agg for next layer) ----------------------
__global__ void k_bn(const float* __restrict__ gamma,
                     const float* __restrict__ beta, int l, int n)
{
    const float invn = 1.f / (float)n;
    int total = n * HH;
    for (int idx = blockIdx.x * blockDim.x + threadIdx.x; idx < total;
         idx += gridDim.x * blockDim.x) {
        int j = idx & (HH - 1);
        float mu  = g_sum[l * HH + j] * invn;
        float var = g_sq[l * HH + j] * invn - mu * mu;
        g_h[idx] = (g_r[idx] - mu) * rsqrtf(var + EPSBN) * gamma[j] + beta[j];
        g_agg[idx] = 0.f;
    }
}

// ---------------- final MLP ---------------------------------------------------
__global__ __launch_bounds__(NT) void k_final(
    const float* __restrict__ Wf, const float* __restrict__ bf,
    const float* __restrict__ Wo, const float* __restrict__ bo,
    float* __restrict__ out, int n)
{
    extern __shared__ float smem[];
    float* As = smem;
    float* Ws = As + 64 * 132;
    const int tid = threadIdx.x;
    const int base = blockIdx.x * 64;

    for (int t = tid; t < 64 * 32; t += NT) {
        int row = t >> 5, j = (t & 31) << 2;
        float4 v = make_float4(0.f, 0.f, 0.f, 0.f);
        if (base + row < n) v = *(const float4*)(g_h + (size_t)(base + row) * HH + j);
        *(float4*)(As + row * 132 + j) = v;
    }

    float acc[4][8] = {};
    gemm_acc<4>(As, 132, Ws, Wf, HH, acc, tid);

    const int ty = tid >> 4, tx = tid & 15, c0 = tx * 8;
    #pragma unroll
    for (int i = 0; i < 4; ++i)
        #pragma unroll
        for (int j = 0; j < 8; ++j)
            As[(ty * 4 + i) * 132 + c0 + j] = fmaxf(acc[i][j] + bf[c0 + j], 0.f);
    __syncthreads();

    const int w = tid >> 5, lane = tid & 31;
    #pragma unroll
    for (int rr = 0; rr < 8; ++rr) {
        int row = w * 8 + rr;
        float sAcc = 0.f;
        #pragma unroll
        for (int qq = 0; qq < 4; ++qq)
            sAcc += As[row * 132 + lane + 32 * qq] * Wo[lane + 32 * qq];
        #pragma unroll
        for (int off = 16; off; off >>= 1)
            sAcc += __shfl_xor_sync(0xffffffffu, sAcc, off);
        if (lane == 0 && base + row < n)
            out[base + row] = 1.f / (1.f + expf(-sAcc));
    }
}

// ---------------- launcher ----------------------------------------------------
extern "C" void kernel_launch(void* const* d_in, const int* in_sizes, int n_in,
                              void* d_out, int out_size)
{
    const float* x    = (const float*)d_in[0];
    const float* ea   = (const float*)d_in[1];
    const int*   ei   = (const int*)  d_in[2];
    const float* W0   = (const float*)d_in[4];
    const float* b0   = (const float*)d_in[5];
    const float* W1   = (const float*)d_in[6];
    const float* b1   = (const float*)d_in[7];
    const float* W1a  = (const float*)d_in[8];
    const float* b1a  = (const float*)d_in[9];
    const float* W1b  = (const float*)d_in[10];
    const float* b1b  = (const float*)d_in[11];
    const float* W2a  = (const float*)d_in[12];
    const float* b2a  = (const float*)d_in[13];
    const float* W2b  = (const float*)d_in[14];
    const float* b2b  = (const float*)d_in[15];
    const float* gam  = (const float*)d_in[16];
    const float* bet  = (const float*)d_in[17];
    const float* Wf   = (const float*)d_in[18];
    const float* bf   = (const float*)d_in[19];
    const float* Wo   = (const float*)d_in[20];
    const float* bo   = (const float*)d_in[21];
    float* out = (float*)d_out;

    const int n = in_sizes[0] / 2;
    const int E = in_sizes[2] / 2;
    const int* srcp = ei;
    const int* dstp = ei + E;

    const int nb_n     = (n + 63) / 64;
    const int ntiles_n = nb_n;
    const int ntiles_e = (E + 63) / 64;
    const int gPers    = 296;   // 2 blocks/SM persistent
    const int gPers1   = 148;   // 1 block/SM persistent

    const size_t SM_IN = (size_t)(64 * 132 + 2048 + 256 + 128 + 128) * 4;
    const size_t SM_P  = (size_t)(128 * 132 + 64 * 132) * 4;                // 101376
    const size_t SM_E  = (size_t)(128 * 132 + 64 * 132 + 256 + 128 + 128 + 128) * 4
                         + 128 * 4;                                          // 104448
    const size_t SM_U1 = (size_t)(256 * 132 + 128 * 132 + 128) * 4;         // 203264
    const size_t SM_U2 = (size_t)(128 * 132 + 64 * 132 + 128) * 4;          // 101888
    const size_t SM_F  = (size_t)(64 * 132 + 2048) * 4;

    cudaFuncSetAttribute(k_edge, cudaFuncAttributeMaxDynamicSharedMemorySize, (int)SM_E);
    cudaFuncSetAttribute(k_precompute, cudaFuncAttributeMaxDynamicSharedMemorySize, (int)SM_P);
    cudaFuncSetAttribute(k_update1, cudaFuncAttributeMaxDynamicSharedMemorySize, (int)SM_U1);
    cudaFuncSetAttribute(k_update2, cudaFuncAttributeMaxDynamicSharedMemorySize, (int)SM_U2);

    k_zero<<<1024, 256>>>(n);
    k_input<<<nb_n, NT, SM_IN>>>(x, W0, b0, W1, b1, dstp, E, n);

    for (int l = 0; l < LL; ++l) {
        const float* W1a_l  = W1a + (size_t)l * 130 * 128;
        const float* W1a_t  = W1a_l + 128 * 128;
        const float* b1a_l  = b1a + (size_t)l * 128;
        const float* W1b_l  = W1b + (size_t)l * 128 * 128;
        const float* b1b_l  = b1b + (size_t)l * 128;
        const float* W2a_l  = W2a + (size_t)l * 256 * 128;
        const float* b2a_l  = b2a + (size_t)l * 128;
        const float* W2b_l  = W2b + (size_t)l * 128 * 128;
        const float* b2b_l  = b2b + (size_t)l * 128;
        const float* gam_l  = gam + (size_t)l * 128;
        const float* bet_l  = bet + (size_t)l * 128;

        k_precompute<<<gPers, NT, SM_P>>>(W1a_l, n, ntiles_n);
        k_edge<<<gPers, NT, SM_E>>>(ea, srcp, dstp, W1a_t, b1a_l, W1b_l, b1b_l,
                                    E, ntiles_e);
        k_update1<<<gPers1, NT, SM_U1>>>(W2a_l, b2a_l, n, ntiles_n);
        k_update2<<<gPers, NT, SM_U2>>>(W2b_l, b2b_l, l, n, ntiles_n);
        k_bn<<<1024, 256>>>(gam_l, bet_l, l, n);
    }

    k_final<<<nb_n, NT, SM_F>>>(Wf, bf, Wo, bo, out, n);
}